// round 8
// baseline (speedup 1.0000x reference)
#include <cuda_runtime.h>
#include <cuda_fp16.h>
#include <stdint.h>

// ============================================================================
// GRU cell via legacy mma.sync (tcgen05 unavailable at plain-sm_103 PTX target).
// R8: cross-chunk software pipelining of MMA fragments. A + gate0-B fragments
// are double-buffered in registers; the full[s+1] wait + ks0 preload for the
// NEXT chunk happens during the current chunk's last ks-step, so the tensor
// queue never drains at chunk boundaries. 1 producer warp (288 threads) to
// raise the per-thread register cap to 227 (demand ~195).
//   r = sigmoid(x@wx_r + hid@wh_r + b...), z = sigmoid(...),
//   n = tanh((x@wx_n + bx_n) + r*(hid@wh_n + bh_n)), out = (1-z)n + z*hid
// B=8192, I=H=1024. fp16 operands, fp32 accum, 4 register accumulator slots.
// ============================================================================

#define TM 128
#define TN 64
#define KC 64
#define STAGES 3
#define CHT 32                 // chunks per tile: 0..15 x-phase, 16..31 hid
#define NTILES 1024            // 64 m-tiles x 16 n-tiles
#define GRID 148
#define PITCH 144              // 128B row + 16B pad (conflict-free ldsm)
#define A_BYTES (128 * PITCH)              // 18432
#define WG_BYTES (64 * PITCH)              // 9216
#define STG (A_BYTES + 3 * WG_BYTES)       // 46080
#define HIDB (2048 + STAGES * STG)         // 140288: hid tiles start
#define HPITCH 272                          // 64 floats + 16B pad
#define HBYTES (128 * HPITCH)              // 34816 per parity
#define SMEM_DYN (HIDB + 2 * HBYTES)       // 209920

#define NTHREADS 288           // 8 consumer warps + 1 producer warp

// fp16 staging (device globals = allocation-free scratch)
__device__ __half g_xh[8192u * 1024u];
__device__ __half g_hh[8192u * 1024u];
__device__ __half g_wxh[3u * 1024u * 1024u];   // [g][h][i] (k contiguous)
__device__ __half g_whh[3u * 1024u * 1024u];

// ---------------------------------------------------------------- helpers ---
__device__ __forceinline__ uint32_t smem_u32(const void* p) {
    uint32_t a;
    asm("{ .reg .u64 t; cvta.to.shared.u64 t, %1; cvt.u32.u64 %0, t; }"
        : "=r"(a) : "l"(p));
    return a;
}

__device__ __forceinline__ void cp16(uint32_t dst, const void* src) {
    asm volatile("cp.async.cg.shared.global [%0], [%1], 16;\n"
                 :: "r"(dst), "l"(src));
}

__device__ __forceinline__ void ldsm4(uint32_t* r, uint32_t addr) {
    asm volatile("ldmatrix.sync.aligned.m8n8.x4.shared.b16 {%0,%1,%2,%3}, [%4];"
                 : "=r"(r[0]), "=r"(r[1]), "=r"(r[2]), "=r"(r[3]) : "r"(addr));
}

__device__ __forceinline__ void mma16816(float* c, const uint32_t* a, const uint32_t* b) {
    asm volatile(
        "mma.sync.aligned.m16n8k16.row.col.f32.f16.f16.f32 "
        "{%0,%1,%2,%3}, {%4,%5,%6,%7}, {%8,%9}, {%0,%1,%2,%3};"
        : "+f"(c[0]), "+f"(c[1]), "+f"(c[2]), "+f"(c[3])
        : "r"(a[0]), "r"(a[1]), "r"(a[2]), "r"(a[3]), "r"(b[0]), "r"(b[1]));
}

__device__ __forceinline__ void mbar_wait(uint32_t mbar, uint32_t parity) {
    asm volatile(
        "{\n\t.reg .pred P1;\n\t"
        "WL_%=:\n\t"
        "mbarrier.try_wait.parity.acquire.cta.shared::cta.b64 P1, [%0], %1, 0x989680;\n\t"
        "@P1 bra.uni WD_%=;\n\t"
        "bra.uni WL_%=;\n\t"
        "WD_%=:\n\t}"
        :: "r"(mbar), "r"(parity) : "memory");
}

__device__ __forceinline__ void mbar_arrive(uint32_t mbar) {
    asm volatile("mbarrier.arrive.shared.b64 _, [%0];" :: "r"(mbar) : "memory");
}

// fragment loaders / MMA blocks
__device__ __forceinline__ void ld_a(uint32_t (&a)[2][4], uint32_t st, int ks,
                                     int lid, int wm) {
#pragma unroll
    for (int mt = 0; mt < 2; mt++) {
        uint32_t arow = wm * 32 + mt * 16 + (lid & 15);
        ldsm4(a[mt], st + arow * PITCH + ks * 32 + (lid >> 4) * 16);
    }
}

__device__ __forceinline__ void ld_b(uint32_t (&b)[2][4], uint32_t st, int g, int ks,
                                     int lid, int wn) {
#pragma unroll
    for (int p = 0; p < 2; p++) {
        uint32_t wrow = wn * 32 + p * 16 + (lid & 7) + ((lid & 16) >> 1);
        ldsm4(b[p], st + A_BYTES + g * WG_BYTES + wrow * PITCH
                      + ((lid >> 3) & 1) * 16 + ks * 32);
    }
}

__device__ __forceinline__ void mma_g(float (&accg)[2][4][4],
                                      uint32_t (&a)[2][4], uint32_t (&b)[2][4]) {
#pragma unroll
    for (int mt = 0; mt < 2; mt++)
#pragma unroll
        for (int nt = 0; nt < 4; nt++)
            mma16816(accg[mt][nt], a[mt], &b[nt >> 1][(nt & 1) * 2]);
}

// ----------------------------------------------------- merged pre-pass ------
__global__ void k_prep(const float* __restrict__ x, const float* __restrict__ hid,
                       const float* __restrict__ wx, const float* __restrict__ wh) {
    const int b = blockIdx.x;
    if (b < 16384) {
        const float* src = (b < 8192) ? x : hid;
        __half* dst = (b < 8192) ? g_xh : g_hh;
        size_t i = ((size_t)(b & 8191) * 256 + threadIdx.x) * 4;
        float4 v = *reinterpret_cast<const float4*>(src + i);
        *reinterpret_cast<__half2*>(dst + i)     = __floats2half2_rn(v.x, v.y);
        *reinterpret_cast<__half2*>(dst + i + 2) = __floats2half2_rn(v.z, v.w);
        return;
    }
    __shared__ float tile[32][33];
    const int bb = b - 16384;
    const int m = bb >> 10;
    const int rem = bb & 1023;
    const int h0 = (rem & 31) * 32;
    const int i0 = (rem >> 5) * 32;
    const float* src = (m < 3) ? (wx + (size_t)m * 1048576)
                               : (wh + (size_t)(m - 3) * 1048576);
    __half* dst = ((m < 3) ? g_wxh : g_whh) + (size_t)(m % 3) * 1048576;
    const int tx = threadIdx.x & 31, ty = threadIdx.x >> 5;
#pragma unroll
    for (int j = 0; j < 32; j += 8)
        tile[ty + j][tx] = src[(size_t)(i0 + ty + j) * 1024 + h0 + tx];
    __syncthreads();
#pragma unroll
    for (int j = 0; j < 32; j += 8)
        dst[(size_t)(h0 + ty + j) * 1024 + i0 + tx] = __float2half_rn(tile[tx][ty + j]);
}

// ------------------------------------------------------------- GEMM kernel ---
// SMEM: [0,1024)      bias sb[4][64] fp32 (per tile, consumer-guarded)
//       [1024,1072)   chunk mbarriers: full[s]=1024+16s, empty[s]=1032+16s
//       [1104,1136)   hid mbarriers: hfull[p]=1104+16p, hempty[p]=1112+16p
//       [2048,140288) chunk stages: A[128][PITCH] + 3 W[64][PITCH] each
//       [140288, ...) hid tiles: parity p at HIDB + p*HBYTES, pitch HPITCH
// acc slots: 0=r, 1=z, 2=gx_n, 3=gh_n.

__global__ void __launch_bounds__(NTHREADS, 1)
k_gru(const float* __restrict__ hid,
      const float* __restrict__ bx, const float* __restrict__ bh,
      float* __restrict__ out) {
    extern __shared__ char smem[];
    const uint32_t sbase = smem_u32(smem);
    const uint32_t mb0 = sbase + 1024;
    const uint32_t hmb = sbase + 1104;
    const uint32_t stg0 = sbase + 2048;

    const int tid = threadIdx.x;
    const int lid = tid & 31;
    const int wid = tid >> 5;
    const int bid = blockIdx.x;

    if (tid < STAGES) {
        asm volatile("mbarrier.init.shared.b64 [%0], 32;" :: "r"(mb0 + tid * 16)     : "memory");
        asm volatile("mbarrier.init.shared.b64 [%0], 8;"  :: "r"(mb0 + tid * 16 + 8) : "memory");
    }
    if (tid >= 32 && tid < 34) {
        int p = tid - 32;
        asm volatile("mbarrier.init.shared.b64 [%0], 32;" :: "r"(hmb + p * 16)     : "memory");
        asm volatile("mbarrier.init.shared.b64 [%0], 8;"  :: "r"(hmb + p * 16 + 8) : "memory");
    }
    __syncthreads();

    if (wid == 8) {
        // ---------------- producer warp (32 threads), continuous ---------------
        const int ptid = tid - 256;               // 0..31
        int c = 0;
        int tt = 0;
        for (int t = bid; t < NTILES; t += GRID, ++tt) {
            const int m0 = (t >> 4) * TM;
            const int n0 = (t & 15) * TN;
            const int p = tt & 1;
            const int r = tt >> 1;
            if (r > 0) mbar_wait(hmb + p * 16 + 8, (r - 1) & 1);   // hempty[p]
            {
                uint32_t hdst = sbase + HIDB + (uint32_t)p * HBYTES;
#pragma unroll 8
                for (int q = 0; q < 64; q++) {      // 2048 cp16: 128 rows x 16
                    int op = ptid + q * 32, row = op >> 4, cg = op & 15;
                    cp16(hdst + row * HPITCH + cg * 16,
                         hid + (size_t)(m0 + row) * 1024 + n0 + cg * 4);
                }
                asm volatile("cp.async.mbarrier.arrive.noinc.shared::cta.b64 [%0];"
                             :: "r"(hmb + p * 16) : "memory");      // hfull[p]
            }
            for (int it = 0; it < CHT; ++it, ++c) {
                const int s = c % STAGES;
                const int rnd = c / STAGES;
                if (rnd > 0) mbar_wait(mb0 + s * 16 + 8, (rnd - 1) & 1);  // empty[s]
                uint32_t st = stg0 + (uint32_t)s * STG;
                const __half* asrc = (it < 16) ? g_xh  : g_hh;
                const __half* wsrc = (it < 16) ? g_wxh : g_whh;
                const int k0 = (it & 15) * KC;
#pragma unroll 8
                for (int q = 0; q < 32; q++) {     // A: 1024 cp16
                    int op = ptid + q * 32, row = op >> 3, cg = op & 7;
                    cp16(st + row * PITCH + cg * 16,
                         asrc + (size_t)(m0 + row) * 1024 + k0 + cg * 8);
                }
#pragma unroll 8
                for (int q = 0; q < 48; q++) {     // W: 1536 cp16
                    int op = ptid + q * 32, g = op >> 9, rr2 = (op >> 3) & 63, cg = op & 7;
                    cp16(st + A_BYTES + g * WG_BYTES + rr2 * PITCH + cg * 16,
                         wsrc + (size_t)g * 1048576 + (size_t)(n0 + rr2) * 1024 + k0 + cg * 8);
                }
                asm volatile("cp.async.mbarrier.arrive.noinc.shared::cta.b64 [%0];"
                             :: "r"(mb0 + s * 16) : "memory");
            }
        }
        return;
    }
    if (wid > 8) return;

    // ------------------- consumer warps (8 warps, 256 threads) ----------------
    const int wm = wid & 3;
    const int wn = wid >> 2;
    float* sb = reinterpret_cast<float*>(smem);
    const int g4 = lid >> 2, t4 = lid & 3;

    // persistent fragment buffers: A and gate0-B double-buffered across ks/chunks
    uint32_t aD[2][2][4];
    uint32_t b0D[2][2][4];
    uint32_t b1[2][4], b2[2][4];

    float acc[4][2][4][4];

    // prologue: chunk 0 / ks 0 fragments
    mbar_wait(mb0 + 0, 0);
    ld_a(aD[0], stg0, 0, lid, wm);
    ld_b(b0D[0], stg0, 0, 0, lid, wn);

    int c = 0;
    int tt = 0;
    for (int t = bid; t < NTILES; t += GRID, ++tt) {
        const int m0 = (t >> 4) * TM;
        const int n0 = (t & 15) * TN;
        const int p = tt & 1;
        const int r = tt >> 1;
        const bool last_tile = (t + GRID >= NTILES);

        asm volatile("bar.sync 1, 256;" ::: "memory");
        if (tid < 64) {
            int h = n0 + tid;
            sb[tid]       = bx[h]        + bh[h];
            sb[64 + tid]  = bx[1024 + h] + bh[1024 + h];
            sb[128 + tid] = bx[2048 + h];
            sb[192 + tid] = bh[2048 + h];
        }
        asm volatile("bar.sync 1, 256;" ::: "memory");

#pragma unroll
        for (int s4 = 0; s4 < 4; s4++)
#pragma unroll
            for (int mt = 0; mt < 2; mt++)
#pragma unroll
                for (int nt = 0; nt < 4; nt++)
#pragma unroll
                    for (int q = 0; q < 4; q++) acc[s4][mt][nt][q] = 0.f;

#pragma unroll 1
        for (int it = 0; it < CHT; ++it, ++c) {
            const int s = c % STAGES;
            const uint32_t st = stg0 + (uint32_t)s * STG;
            const bool xph = (it < 16);
            const bool last_chunk = last_tile && (it == CHT - 1);
#pragma unroll
            for (int ks = 0; ks < 4; ks++) {
                const int pk = ks & 1;
                ld_b(b1, st, 1, ks, lid, wn);
                mma_g(acc[0], aD[pk], b0D[pk]);          // r gate
                ld_b(b2, st, 2, ks, lid, wn);
                mma_g(acc[1], aD[pk], b1);               // z gate
                if (ks < 3) {
                    ld_a(aD[pk ^ 1], st, ks + 1, lid, wm);
                    ld_b(b0D[pk ^ 1], st, 0, ks + 1, lid, wn);
                } else if (!last_chunk) {
                    const int cn = c + 1, sn = cn % STAGES;
                    mbar_wait(mb0 + sn * 16, (cn / STAGES) & 1);
                    const uint32_t stn = stg0 + (uint32_t)sn * STG;
                    ld_a(aD[pk ^ 1], stn, 0, lid, wm);
                    ld_b(b0D[pk ^ 1], stn, 0, 0, lid, wn);
                }
                if (xph) mma_g(acc[2], aD[pk], b2);      // n gate (x part)
                else     mma_g(acc[3], aD[pk], b2);      // n gate (hid part)
            }
            if (lid == 0) mbar_arrive(mb0 + s * 16 + 8);
        }

        // ---- fused GRU epilogue (hid from SMEM; producer streams next tile) ----
        mbar_wait(hmb + p * 16, r & 1);            // hfull[p]
        const char* hbuf = smem + HIDB + (size_t)p * HBYTES;
#pragma unroll
        for (int mt = 0; mt < 2; mt++)
#pragma unroll
            for (int nt = 0; nt < 4; nt++)
#pragma unroll
                for (int hf = 0; hf < 2; hf++) {
                    int rloc = wm * 32 + mt * 16 + g4 + hf * 8;
                    int coll = wn * 32 + nt * 8 + t4 * 2;
                    float2 h2 = *reinterpret_cast<const float2*>(
                        hbuf + rloc * HPITCH + coll * 4);
                    size_t base = (size_t)(m0 + rloc) * 1024 + n0 + coll;
                    float o[2];
#pragma unroll
                    for (int j = 0; j < 2; j++) {
                        int ri = hf * 2 + j;
                        float pr = acc[0][mt][nt][ri] + sb[coll + j];
                        float pz = acc[1][mt][nt][ri] + sb[64 + coll + j];
                        float rr = __fdividef(1.f, 1.f + __expf(-pr));
                        float zz = __fdividef(1.f, 1.f + __expf(-pz));
                        float pn = (acc[2][mt][nt][ri] + sb[128 + coll + j])
                                 + rr * (acc[3][mt][nt][ri] + sb[192 + coll + j]);
                        float ttv = __expf(-2.f * fabsf(pn));
                        float nn = copysignf(__fdividef(1.f - ttv, 1.f + ttv), pn);
                        float hv = j ? h2.y : h2.x;
                        o[j] = nn + zz * (hv - nn);
                    }
                    *reinterpret_cast<float2*>(out + base) = make_float2(o[0], o[1]);
                }
        if (lid == 0) mbar_arrive(hmb + p * 16 + 8);   // hempty[p]
    }
}

// --------------------------------------------------------------- launcher ---
extern "C" void kernel_launch(void* const* d_in, const int* in_sizes, int n_in,
                              void* d_out, int out_size) {
    const float* x   = (const float*)d_in[0];
    const float* hid = (const float*)d_in[1];
    const float* wx  = (const float*)d_in[2];
    const float* wh  = (const float*)d_in[3];
    const float* bx  = (const float*)d_in[4];
    const float* bh  = (const float*)d_in[5];
    float* out = (float*)d_out;

    cudaFuncSetAttribute(k_gru, cudaFuncAttributeMaxDynamicSharedMemorySize, SMEM_DYN);

    k_prep<<<22528, 256>>>(x, hid, wx, wh);
    k_gru<<<GRID, NTHREADS, SMEM_DYN>>>(hid, bx, bh, out);
}

// round 9
// speedup vs baseline: 1.2832x; 1.2832x over previous
#include <cuda_runtime.h>
#include <cuda_fp16.h>
#include <stdint.h>

// ============================================================================
// GRU cell via legacy mma.sync (tcgen05 unavailable at plain-sm_103 PTX target).
// R9 = R7 (best: 270 µs) + ks-STAGGER: the two consumer warps sharing each
// SMSP (wid, wid+4 — opposite wn) process the 4 ks-steps of a chunk in
// rotated order (wn=0: 0,1,2,3; wn=1: 2,3,0,1). ks order is commutative for
// the accumulation, and anti-aligning the warps' ldsm phases lets one warp's
// MMA burst cover the other's ldsm->MMA dependency shadow.
// R8's manual cross-chunk register pipelining REVERTED (ptxas spilled).
//   r = sigmoid(x@wx_r + hid@wh_r + b...), z = sigmoid(...),
//   n = tanh((x@wx_n + bx_n) + r*(hid@wh_n + bh_n)), out = (1-z)n + z*hid
// B=8192, I=H=1024. fp16 operands, fp32 accum, 4 register accumulator slots.
// ============================================================================

#define TM 128
#define TN 64
#define KC 64
#define STAGES 3
#define CHT 32                 // chunks per tile: 0..15 x-phase, 16..31 hid
#define NTILES 1024            // 64 m-tiles x 16 n-tiles
#define GRID 148
#define PITCH 144              // 128B row + 16B pad (conflict-free ldsm)
#define A_BYTES (128 * PITCH)              // 18432
#define WG_BYTES (64 * PITCH)              // 9216
#define STG (A_BYTES + 3 * WG_BYTES)       // 46080
#define HIDB (2048 + STAGES * STG)         // 140288: hid tiles start
#define HPITCH 272                          // 64 floats + 16B pad
#define HBYTES (128 * HPITCH)              // 34816 per parity
#define SMEM_DYN (HIDB + 2 * HBYTES)       // 209920

#define NTHREADS 320           // 8 consumer warps + 2 producer warps

// fp16 staging (device globals = allocation-free scratch)
__device__ __half g_xh[8192u * 1024u];
__device__ __half g_hh[8192u * 1024u];
__device__ __half g_wxh[3u * 1024u * 1024u];   // [g][h][i] (k contiguous)
__device__ __half g_whh[3u * 1024u * 1024u];

// ---------------------------------------------------------------- helpers ---
__device__ __forceinline__ uint32_t smem_u32(const void* p) {
    uint32_t a;
    asm("{ .reg .u64 t; cvta.to.shared.u64 t, %1; cvt.u32.u64 %0, t; }"
        : "=r"(a) : "l"(p));
    return a;
}

__device__ __forceinline__ void cp16(uint32_t dst, const void* src) {
    asm volatile("cp.async.cg.shared.global [%0], [%1], 16;\n"
                 :: "r"(dst), "l"(src));
}

__device__ __forceinline__ void ldsm4(uint32_t* r, uint32_t addr) {
    asm volatile("ldmatrix.sync.aligned.m8n8.x4.shared.b16 {%0,%1,%2,%3}, [%4];"
                 : "=r"(r[0]), "=r"(r[1]), "=r"(r[2]), "=r"(r[3]) : "r"(addr));
}

__device__ __forceinline__ void mma16816(float* c, const uint32_t* a, const uint32_t* b) {
    asm volatile(
        "mma.sync.aligned.m16n8k16.row.col.f32.f16.f16.f32 "
        "{%0,%1,%2,%3}, {%4,%5,%6,%7}, {%8,%9}, {%0,%1,%2,%3};"
        : "+f"(c[0]), "+f"(c[1]), "+f"(c[2]), "+f"(c[3])
        : "r"(a[0]), "r"(a[1]), "r"(a[2]), "r"(a[3]), "r"(b[0]), "r"(b[1]));
}

__device__ __forceinline__ void mbar_wait(uint32_t mbar, uint32_t parity) {
    asm volatile(
        "{\n\t.reg .pred P1;\n\t"
        "WL_%=:\n\t"
        "mbarrier.try_wait.parity.acquire.cta.shared::cta.b64 P1, [%0], %1, 0x989680;\n\t"
        "@P1 bra.uni WD_%=;\n\t"
        "bra.uni WL_%=;\n\t"
        "WD_%=:\n\t}"
        :: "r"(mbar), "r"(parity) : "memory");
}

__device__ __forceinline__ void mbar_arrive(uint32_t mbar) {
    asm volatile("mbarrier.arrive.shared.b64 _, [%0];" :: "r"(mbar) : "memory");
}

// ----------------------------------------------------- merged pre-pass ------
__global__ void k_prep(const float* __restrict__ x, const float* __restrict__ hid,
                       const float* __restrict__ wx, const float* __restrict__ wh) {
    const int b = blockIdx.x;
    if (b < 16384) {
        const float* src = (b < 8192) ? x : hid;
        __half* dst = (b < 8192) ? g_xh : g_hh;
        size_t i = ((size_t)(b & 8191) * 256 + threadIdx.x) * 4;
        float4 v = *reinterpret_cast<const float4*>(src + i);
        *reinterpret_cast<__half2*>(dst + i)     = __floats2half2_rn(v.x, v.y);
        *reinterpret_cast<__half2*>(dst + i + 2) = __floats2half2_rn(v.z, v.w);
        return;
    }
    __shared__ float tile[32][33];
    const int bb = b - 16384;
    const int m = bb >> 10;
    const int rem = bb & 1023;
    const int h0 = (rem & 31) * 32;
    const int i0 = (rem >> 5) * 32;
    const float* src = (m < 3) ? (wx + (size_t)m * 1048576)
                               : (wh + (size_t)(m - 3) * 1048576);
    __half* dst = ((m < 3) ? g_wxh : g_whh) + (size_t)(m % 3) * 1048576;
    const int tx = threadIdx.x & 31, ty = threadIdx.x >> 5;
#pragma unroll
    for (int j = 0; j < 32; j += 8)
        tile[ty + j][tx] = src[(size_t)(i0 + ty + j) * 1024 + h0 + tx];
    __syncthreads();
#pragma unroll
    for (int j = 0; j < 32; j += 8)
        dst[(size_t)(h0 + ty + j) * 1024 + i0 + tx] = __float2half_rn(tile[tx][ty + j]);
}

// ------------------------------------------------------------- GEMM kernel ---
// SMEM: [0,1024)      bias sb[4][64] fp32 (per tile, consumer-guarded)
//       [1024,1072)   chunk mbarriers: full[s]=1024+16s, empty[s]=1032+16s
//       [1104,1136)   hid mbarriers: hfull[p]=1104+16p, hempty[p]=1112+16p
//       [2048,140288) chunk stages: A[128][PITCH] + 3 W[64][PITCH] each
//       [140288, ...) hid tiles: parity p at HIDB + p*HBYTES, pitch HPITCH
// acc slots: 0=r, 1=z, 2=gx_n, 3=gh_n.

template<int NS>
__device__ __forceinline__ void compute_chunk(float (&acc)[4][2][4][4],
                                              uint32_t st, int lid, int wm, int wn) {
    // ks-stagger: SMSP partners (wn=0 vs wn=1) start 2 ks-steps apart so their
    // ldsm dependency shadows anti-align with each other's MMA bursts.
    const int kbase = wn * 2;
#pragma unroll
    for (int ksi = 0; ksi < 4; ksi++) {
        const int ks = (ksi + kbase) & 3;
        uint32_t af[2][4];
        uint32_t bf[3][2][4];
#pragma unroll
        for (int mt = 0; mt < 2; mt++) {
            uint32_t arow = wm * 32 + mt * 16 + (lid & 15);
            ldsm4(af[mt], st + arow * PITCH + ks * 32 + (lid >> 4) * 16);
        }
#pragma unroll
        for (int g = 0; g < 3; g++)
#pragma unroll
            for (int p = 0; p < 2; p++) {
                uint32_t wrow = wn * 32 + p * 16 + (lid & 7) + ((lid & 16) >> 1);
                ldsm4(bf[g][p], st + A_BYTES + g * WG_BYTES + wrow * PITCH
                                 + ((lid >> 3) & 1) * 16 + ks * 32);
            }
#pragma unroll
        for (int g = 0; g < 3; g++) {
            const int slot = (g == 0) ? 0 : (g == 1) ? 1 : NS;
#pragma unroll
            for (int mt = 0; mt < 2; mt++)
#pragma unroll
                for (int nt = 0; nt < 4; nt++)
                    mma16816(acc[slot][mt][nt], af[mt], &bf[g][nt >> 1][(nt & 1) * 2]);
        }
    }
}

__global__ void __launch_bounds__(NTHREADS, 1)
k_gru(const float* __restrict__ hid,
      const float* __restrict__ bx, const float* __restrict__ bh,
      float* __restrict__ out) {
    extern __shared__ char smem[];
    const uint32_t sbase = smem_u32(smem);
    const uint32_t mb0 = sbase + 1024;
    const uint32_t hmb = sbase + 1104;
    const uint32_t stg0 = sbase + 2048;

    const int tid = threadIdx.x;
    const int lid = tid & 31;
    const int wid = tid >> 5;
    const int bid = blockIdx.x;

    if (tid < STAGES) {
        asm volatile("mbarrier.init.shared.b64 [%0], 64;" :: "r"(mb0 + tid * 16)     : "memory");
        asm volatile("mbarrier.init.shared.b64 [%0], 8;"  :: "r"(mb0 + tid * 16 + 8) : "memory");
    }
    if (tid >= 32 && tid < 34) {
        int p = tid - 32;
        asm volatile("mbarrier.init.shared.b64 [%0], 64;" :: "r"(hmb + p * 16)     : "memory");
        asm volatile("mbarrier.init.shared.b64 [%0], 8;"  :: "r"(hmb + p * 16 + 8) : "memory");
    }
    __syncthreads();

    if (wid >= 8) {
        // ---------------- producer warps: continuous across tiles --------------
        const int ptid = tid - 256;               // 0..63
        int c = 0;                                 // global chunk counter
        int tt = 0;                                // tile sequence counter
        for (int t = bid; t < NTILES; t += GRID, ++tt) {
            const int m0 = (t >> 4) * TM;
            const int n0 = (t & 15) * TN;
            const int p = tt & 1;
            const int r = tt >> 1;
            // stage hid tile for the epilogue (double-buffered)
            if (r > 0) mbar_wait(hmb + p * 16 + 8, (r - 1) & 1);   // hempty[p]
            {
                uint32_t hdst = sbase + HIDB + (uint32_t)p * HBYTES;
#pragma unroll
                for (int q = 0; q < 32; q++) {      // 2048 cp16: 128 rows x 16
                    int op = ptid + q * 64, row = op >> 4, cg = op & 15;
                    cp16(hdst + row * HPITCH + cg * 16,
                         hid + (size_t)(m0 + row) * 1024 + n0 + cg * 4);
                }
                asm volatile("cp.async.mbarrier.arrive.noinc.shared::cta.b64 [%0];"
                             :: "r"(hmb + p * 16) : "memory");      // hfull[p]
            }
            for (int it = 0; it < CHT; ++it, ++c) {
                const int s = c % STAGES;
                const int rnd = c / STAGES;
                if (rnd > 0) mbar_wait(mb0 + s * 16 + 8, (rnd - 1) & 1);  // empty[s]
                uint32_t st = stg0 + (uint32_t)s * STG;
                const __half* asrc = (it < 16) ? g_xh  : g_hh;
                const __half* wsrc = (it < 16) ? g_wxh : g_whh;
                const int k0 = (it & 15) * KC;
#pragma unroll
                for (int q = 0; q < 16; q++) {     // A: 1024 cp16
                    int op = ptid + q * 64, row = op >> 3, cg = op & 7;
                    cp16(st + row * PITCH + cg * 16,
                         asrc + (size_t)(m0 + row) * 1024 + k0 + cg * 8);
                }
#pragma unroll
                for (int q = 0; q < 24; q++) {     // W: 1536 cp16
                    int op = ptid + q * 64, g = op >> 9, rr2 = (op >> 3) & 63, cg = op & 7;
                    cp16(st + A_BYTES + g * WG_BYTES + rr2 * PITCH + cg * 16,
                         wsrc + (size_t)g * 1048576 + (size_t)(n0 + rr2) * 1024 + k0 + cg * 8);
                }
                asm volatile("cp.async.mbarrier.arrive.noinc.shared::cta.b64 [%0];"
                             :: "r"(mb0 + s * 16) : "memory");
            }
        }
        return;
    }

    // ------------------- consumer warps (8 warps, 256 threads) ----------------
    const int wm = wid & 3;
    const int wn = wid >> 2;
    float* sb = reinterpret_cast<float*>(smem);
    const int g4 = lid >> 2, t4 = lid & 3;

    int c = 0;
    int tt = 0;
    for (int t = bid; t < NTILES; t += GRID, ++tt) {
        const int m0 = (t >> 4) * TM;
        const int n0 = (t & 15) * TN;
        const int p = tt & 1;
        const int r = tt >> 1;

        // guard: previous tile's epilogue (sb readers) done before rewrite
        asm volatile("bar.sync 1, 256;" ::: "memory");
        if (tid < 64) {
            int h = n0 + tid;
            sb[tid]       = bx[h]        + bh[h];
            sb[64 + tid]  = bx[1024 + h] + bh[1024 + h];
            sb[128 + tid] = bx[2048 + h];
            sb[192 + tid] = bh[2048 + h];
        }
        asm volatile("bar.sync 1, 256;" ::: "memory");

        float acc[4][2][4][4];
#pragma unroll
        for (int s = 0; s < 4; s++)
#pragma unroll
            for (int mt = 0; mt < 2; mt++)
#pragma unroll
                for (int nt = 0; nt < 4; nt++)
#pragma unroll
                    for (int q = 0; q < 4; q++) acc[s][mt][nt][q] = 0.f;

#pragma unroll 1
        for (int it = 0; it < 16; ++it, ++c) {     // x-phase: n-gate -> slot 2
            const int s = c % STAGES;
            mbar_wait(mb0 + s * 16, (c / STAGES) & 1);
            compute_chunk<2>(acc, stg0 + (uint32_t)s * STG, lid, wm, wn);
            if (lid == 0) mbar_arrive(mb0 + s * 16 + 8);
        }
#pragma unroll 1
        for (int it = 16; it < CHT; ++it, ++c) {   // hid-phase: n-gate -> slot 3
            const int s = c % STAGES;
            mbar_wait(mb0 + s * 16, (c / STAGES) & 1);
            compute_chunk<3>(acc, stg0 + (uint32_t)s * STG, lid, wm, wn);
            if (lid == 0) mbar_arrive(mb0 + s * 16 + 8);
        }

        // ---- fused GRU epilogue (hid from SMEM; producers stream next tile) ----
        mbar_wait(hmb + p * 16, r & 1);            // hfull[p]
        const char* hbuf = smem + HIDB + (size_t)p * HBYTES;
#pragma unroll
        for (int mt = 0; mt < 2; mt++)
#pragma unroll
            for (int nt = 0; nt < 4; nt++)
#pragma unroll
                for (int hf = 0; hf < 2; hf++) {
                    int rloc = wm * 32 + mt * 16 + g4 + hf * 8;
                    int coll = wn * 32 + nt * 8 + t4 * 2;
                    float2 h2 = *reinterpret_cast<const float2*>(
                        hbuf + rloc * HPITCH + coll * 4);
                    size_t base = (size_t)(m0 + rloc) * 1024 + n0 + coll;
                    float o[2];
#pragma unroll
                    for (int j = 0; j < 2; j++) {
                        int ri = hf * 2 + j;
                        float pr = acc[0][mt][nt][ri] + sb[coll + j];
                        float pz = acc[1][mt][nt][ri] + sb[64 + coll + j];
                        float rr = __fdividef(1.f, 1.f + __expf(-pr));
                        float zz = __fdividef(1.f, 1.f + __expf(-pz));
                        float pn = (acc[2][mt][nt][ri] + sb[128 + coll + j])
                                 + rr * (acc[3][mt][nt][ri] + sb[192 + coll + j]);
                        float ttv = __expf(-2.f * fabsf(pn));
                        float nn = copysignf(__fdividef(1.f - ttv, 1.f + ttv), pn);
                        float hv = j ? h2.y : h2.x;
                        o[j] = nn + zz * (hv - nn);
                    }
                    *reinterpret_cast<float2*>(out + base) = make_float2(o[0], o[1]);
                }
        if (lid == 0) mbar_arrive(hmb + p * 16 + 8);   // hempty[p]
    }
}

// --------------------------------------------------------------- launcher ---
extern "C" void kernel_launch(void* const* d_in, const int* in_sizes, int n_in,
                              void* d_out, int out_size) {
    const float* x   = (const float*)d_in[0];
    const float* hid = (const float*)d_in[1];
    const float* wx  = (const float*)d_in[2];
    const float* wh  = (const float*)d_in[3];
    const float* bx  = (const float*)d_in[4];
    const float* bh  = (const float*)d_in[5];
    float* out = (float*)d_out;

    cudaFuncSetAttribute(k_gru, cudaFuncAttributeMaxDynamicSharedMemorySize, SMEM_DYN);

    k_prep<<<22528, 256>>>(x, hid, wx, wh);
    k_gru<<<GRID, NTHREADS, SMEM_DYN>>>(hid, bx, bh, out);
}

// round 10
// speedup vs baseline: 1.3196x; 1.0284x over previous
#include <cuda_runtime.h>
#include <cuda_fp16.h>
#include <stdint.h>

// ============================================================================
// GRU cell via legacy mma.sync (tcgen05 unavailable at plain-sm_103 PTX target).
// R10 = R7 core (best passing structure) + KC=128 / STAGES=2: halves the
// number of chunk boundaries (mbar_wait wakeup + cold ldsm ramp paid per
// boundary by both SMSP-resident warps). Single fp32 hid buffer, loaded by
// the producer AFTER chunk 2 of each tile so the hempty wait never stalls
// the chunk ring. R9 ks-stagger reverted (falsified).
//   r = sigmoid(x@wx_r + hid@wh_r + b...), z = sigmoid(...),
//   n = tanh((x@wx_n + bx_n) + r*(hid@wh_n + bh_n)), out = (1-z)n + z*hid
// B=8192, I=H=1024. fp16 operands, fp32 accum, 4 register accumulator slots.
// CTA tile 128x64: 8 consumer warps (32x32) + 2 producer warps. Persistent.
// ============================================================================

#define TM 128
#define TN 64
#define KC 128
#define STAGES 2
#define CHT 16                 // chunks per tile: 0..7 x-phase, 8..15 hid
#define NTILES 1024            // 64 m-tiles x 16 n-tiles
#define GRID 148
#define PITCH 272              // 256B row + 16B pad (conflict-free ldsm)
#define A_BYTES (128 * PITCH)              // 34816
#define WG_BYTES (64 * PITCH)              // 17408
#define STG (A_BYTES + 3 * WG_BYTES)       // 87040
#define HIDB (2048 + STAGES * STG)         // 176128: hid tile (single buffer)
#define HPITCH 272                          // 64 floats + 16B pad
#define HBYTES (128 * HPITCH)              // 34816
#define SMEM_DYN (HIDB + HBYTES)           // 210944

#define NTHREADS 320           // 8 consumer warps + 2 producer warps

// fp16 staging (device globals = allocation-free scratch)
__device__ __half g_xh[8192u * 1024u];
__device__ __half g_hh[8192u * 1024u];
__device__ __half g_wxh[3u * 1024u * 1024u];   // [g][h][i] (k contiguous)
__device__ __half g_whh[3u * 1024u * 1024u];

// ---------------------------------------------------------------- helpers ---
__device__ __forceinline__ uint32_t smem_u32(const void* p) {
    uint32_t a;
    asm("{ .reg .u64 t; cvta.to.shared.u64 t, %1; cvt.u32.u64 %0, t; }"
        : "=r"(a) : "l"(p));
    return a;
}

__device__ __forceinline__ void cp16(uint32_t dst, const void* src) {
    asm volatile("cp.async.cg.shared.global [%0], [%1], 16;\n"
                 :: "r"(dst), "l"(src));
}

__device__ __forceinline__ void ldsm4(uint32_t* r, uint32_t addr) {
    asm volatile("ldmatrix.sync.aligned.m8n8.x4.shared.b16 {%0,%1,%2,%3}, [%4];"
                 : "=r"(r[0]), "=r"(r[1]), "=r"(r[2]), "=r"(r[3]) : "r"(addr));
}

__device__ __forceinline__ void mma16816(float* c, const uint32_t* a, const uint32_t* b) {
    asm volatile(
        "mma.sync.aligned.m16n8k16.row.col.f32.f16.f16.f32 "
        "{%0,%1,%2,%3}, {%4,%5,%6,%7}, {%8,%9}, {%0,%1,%2,%3};"
        : "+f"(c[0]), "+f"(c[1]), "+f"(c[2]), "+f"(c[3])
        : "r"(a[0]), "r"(a[1]), "r"(a[2]), "r"(a[3]), "r"(b[0]), "r"(b[1]));
}

__device__ __forceinline__ void mbar_wait(uint32_t mbar, uint32_t parity) {
    asm volatile(
        "{\n\t.reg .pred P1;\n\t"
        "WL_%=:\n\t"
        "mbarrier.try_wait.parity.acquire.cta.shared::cta.b64 P1, [%0], %1, 0x989680;\n\t"
        "@P1 bra.uni WD_%=;\n\t"
        "bra.uni WL_%=;\n\t"
        "WD_%=:\n\t}"
        :: "r"(mbar), "r"(parity) : "memory");
}

__device__ __forceinline__ void mbar_arrive(uint32_t mbar) {
    asm volatile("mbarrier.arrive.shared.b64 _, [%0];" :: "r"(mbar) : "memory");
}

// ----------------------------------------------------- merged pre-pass ------
__global__ void k_prep(const float* __restrict__ x, const float* __restrict__ hid,
                       const float* __restrict__ wx, const float* __restrict__ wh) {
    const int b = blockIdx.x;
    if (b < 16384) {
        const float* src = (b < 8192) ? x : hid;
        __half* dst = (b < 8192) ? g_xh : g_hh;
        size_t i = ((size_t)(b & 8191) * 256 + threadIdx.x) * 4;
        float4 v = *reinterpret_cast<const float4*>(src + i);
        *reinterpret_cast<__half2*>(dst + i)     = __floats2half2_rn(v.x, v.y);
        *reinterpret_cast<__half2*>(dst + i + 2) = __floats2half2_rn(v.z, v.w);
        return;
    }
    __shared__ float tile[32][33];
    const int bb = b - 16384;
    const int m = bb >> 10;
    const int rem = bb & 1023;
    const int h0 = (rem & 31) * 32;
    const int i0 = (rem >> 5) * 32;
    const float* src = (m < 3) ? (wx + (size_t)m * 1048576)
                               : (wh + (size_t)(m - 3) * 1048576);
    __half* dst = ((m < 3) ? g_wxh : g_whh) + (size_t)(m % 3) * 1048576;
    const int tx = threadIdx.x & 31, ty = threadIdx.x >> 5;
#pragma unroll
    for (int j = 0; j < 32; j += 8)
        tile[ty + j][tx] = src[(size_t)(i0 + ty + j) * 1024 + h0 + tx];
    __syncthreads();
#pragma unroll
    for (int j = 0; j < 32; j += 8)
        dst[(size_t)(h0 + ty + j) * 1024 + i0 + tx] = __float2half_rn(tile[tx][ty + j]);
}

// ------------------------------------------------------------- GEMM kernel ---
// SMEM: [0,1024)      bias sb[4][64] fp32 (per tile, consumer-guarded)
//       [1024,1056)   chunk mbarriers: full[s]=1024+16s, empty[s]=1032+16s
//       [1104,1120)   hid mbarriers: hfull=1104, hempty=1112
//       [2048,176128) chunk stages: A[128][PITCH] + 3 W[64][PITCH] each
//       [176128, ...) hid tile (single buffer), pitch HPITCH
// acc slots: 0=r, 1=z, 2=gx_n, 3=gh_n.

template<int NS>
__device__ __forceinline__ void compute_chunk(float (&acc)[4][2][4][4],
                                              uint32_t st, int lid, int wm, int wn) {
#pragma unroll
    for (int ks = 0; ks < 8; ks++) {
        uint32_t af[2][4];
        uint32_t bf[3][2][4];
#pragma unroll
        for (int mt = 0; mt < 2; mt++) {
            uint32_t arow = wm * 32 + mt * 16 + (lid & 15);
            ldsm4(af[mt], st + arow * PITCH + ks * 32 + (lid >> 4) * 16);
        }
#pragma unroll
        for (int g = 0; g < 3; g++)
#pragma unroll
            for (int p = 0; p < 2; p++) {
                uint32_t wrow = wn * 32 + p * 16 + (lid & 7) + ((lid & 16) >> 1);
                ldsm4(bf[g][p], st + A_BYTES + g * WG_BYTES + wrow * PITCH
                                 + ((lid >> 3) & 1) * 16 + ks * 32);
            }
#pragma unroll
        for (int g = 0; g < 3; g++) {
            const int slot = (g == 0) ? 0 : (g == 1) ? 1 : NS;
#pragma unroll
            for (int mt = 0; mt < 2; mt++)
#pragma unroll
                for (int nt = 0; nt < 4; nt++)
                    mma16816(acc[slot][mt][nt], af[mt], &bf[g][nt >> 1][(nt & 1) * 2]);
        }
    }
}

__global__ void __launch_bounds__(NTHREADS, 1)
k_gru(const float* __restrict__ hid,
      const float* __restrict__ bx, const float* __restrict__ bh,
      float* __restrict__ out) {
    extern __shared__ char smem[];
    const uint32_t sbase = smem_u32(smem);
    const uint32_t mb0 = sbase + 1024;
    const uint32_t hmb = sbase + 1104;
    const uint32_t stg0 = sbase + 2048;

    const int tid = threadIdx.x;
    const int lid = tid & 31;
    const int wid = tid >> 5;
    const int bid = blockIdx.x;

    if (tid < STAGES) {
        asm volatile("mbarrier.init.shared.b64 [%0], 64;" :: "r"(mb0 + tid * 16)     : "memory");
        asm volatile("mbarrier.init.shared.b64 [%0], 8;"  :: "r"(mb0 + tid * 16 + 8) : "memory");
    }
    if (tid == 32) {
        asm volatile("mbarrier.init.shared.b64 [%0], 64;" :: "r"(hmb)     : "memory");
        asm volatile("mbarrier.init.shared.b64 [%0], 8;"  :: "r"(hmb + 8) : "memory");
    }
    __syncthreads();

    if (wid >= 8) {
        // ---------------- producer warps: continuous across tiles --------------
        const int ptid = tid - 256;               // 0..63
        int c = 0;                                 // global chunk counter
        int tt = 0;                                // tile sequence counter
        for (int t = bid; t < NTILES; t += GRID, ++tt) {
            const int m0 = (t >> 4) * TM;
            const int n0 = (t & 15) * TN;
            for (int it = 0; it < CHT; ++it, ++c) {
                // deferred hid staging: by it==2, previous tile's epilogue
                // (which signals hempty) has already completed, so this wait
                // never blocks the chunk ring.
                if (it == 2) {
                    if (tt > 0) mbar_wait(hmb + 8, (tt - 1) & 1);   // hempty
                    uint32_t hdst = sbase + HIDB;
#pragma unroll
                    for (int q = 0; q < 32; q++) {  // 2048 cp16: 128 rows x 256B
                        int op = ptid + q * 64, row = op >> 4, cg = op & 15;
                        cp16(hdst + row * HPITCH + cg * 16,
                             hid + (size_t)(m0 + row) * 1024 + n0 + cg * 4);
                    }
                    asm volatile("cp.async.mbarrier.arrive.noinc.shared::cta.b64 [%0];"
                                 :: "r"(hmb) : "memory");           // hfull
                }
                const int s = c & 1;
                const int rnd = c >> 1;
                if (rnd > 0) mbar_wait(mb0 + s * 16 + 8, (rnd - 1) & 1);  // empty[s]
                uint32_t st = stg0 + (uint32_t)s * STG;
                const __half* asrc = (it < 8) ? g_xh  : g_hh;
                const __half* wsrc = (it < 8) ? g_wxh : g_whh;
                const int k0 = (it & 7) * KC;
#pragma unroll
                for (int q = 0; q < 32; q++) {     // A: 2048 cp16
                    int op = ptid + q * 64, row = op >> 4, cg = op & 15;
                    cp16(st + row * PITCH + cg * 16,
                         asrc + (size_t)(m0 + row) * 1024 + k0 + cg * 8);
                }
#pragma unroll
                for (int q = 0; q < 48; q++) {     // W: 3072 cp16
                    int op = ptid + q * 64, g = op >> 10, rr2 = (op >> 4) & 63, cg = op & 15;
                    cp16(st + A_BYTES + g * WG_BYTES + rr2 * PITCH + cg * 16,
                         wsrc + (size_t)g * 1048576 + (size_t)(n0 + rr2) * 1024 + k0 + cg * 8);
                }
                asm volatile("cp.async.mbarrier.arrive.noinc.shared::cta.b64 [%0];"
                             :: "r"(mb0 + s * 16) : "memory");
            }
        }
        return;
    }

    // ------------------- consumer warps (8 warps, 256 threads) ----------------
    const int wm = wid & 3;
    const int wn = wid >> 2;
    float* sb = reinterpret_cast<float*>(smem);
    const int g4 = lid >> 2, t4 = lid & 3;

    int c = 0;
    int tt = 0;
    for (int t = bid; t < NTILES; t += GRID, ++tt) {
        const int m0 = (t >> 4) * TM;
        const int n0 = (t & 15) * TN;

        // guard: previous tile's epilogue (sb readers) done before rewrite
        asm volatile("bar.sync 1, 256;" ::: "memory");
        if (tid < 64) {
            int h = n0 + tid;
            sb[tid]       = bx[h]        + bh[h];
            sb[64 + tid]  = bx[1024 + h] + bh[1024 + h];
            sb[128 + tid] = bx[2048 + h];
            sb[192 + tid] = bh[2048 + h];
        }
        asm volatile("bar.sync 1, 256;" ::: "memory");

        float acc[4][2][4][4];
#pragma unroll
        for (int s = 0; s < 4; s++)
#pragma unroll
            for (int mt = 0; mt < 2; mt++)
#pragma unroll
                for (int nt = 0; nt < 4; nt++)
#pragma unroll
                    for (int q = 0; q < 4; q++) acc[s][mt][nt][q] = 0.f;

#pragma unroll 1
        for (int it = 0; it < 8; ++it, ++c) {      // x-phase: n-gate -> slot 2
            const int s = c & 1;
            mbar_wait(mb0 + s * 16, (c >> 1) & 1);
            compute_chunk<2>(acc, stg0 + (uint32_t)s * STG, lid, wm, wn);
            if (lid == 0) mbar_arrive(mb0 + s * 16 + 8);
        }
#pragma unroll 1
        for (int it = 8; it < CHT; ++it, ++c) {    // hid-phase: n-gate -> slot 3
            const int s = c & 1;
            mbar_wait(mb0 + s * 16, (c >> 1) & 1);
            compute_chunk<3>(acc, stg0 + (uint32_t)s * STG, lid, wm, wn);
            if (lid == 0) mbar_arrive(mb0 + s * 16 + 8);
        }

        // ---- fused GRU epilogue (hid from SMEM; producers stream next tile) ----
        mbar_wait(hmb, tt & 1);                    // hfull, completion #tt
        const char* hbuf = smem + HIDB;
#pragma unroll
        for (int mt = 0; mt < 2; mt++)
#pragma unroll
            for (int nt = 0; nt < 4; nt++)
#pragma unroll
                for (int hf = 0; hf < 2; hf++) {
                    int rloc = wm * 32 + mt * 16 + g4 + hf * 8;
                    int coll = wn * 32 + nt * 8 + t4 * 2;
                    float2 h2 = *reinterpret_cast<const float2*>(
                        hbuf + rloc * HPITCH + coll * 4);
                    size_t base = (size_t)(m0 + rloc) * 1024 + n0 + coll;
                    float o[2];
#pragma unroll
                    for (int j = 0; j < 2; j++) {
                        int ri = hf * 2 + j;
                        float pr = acc[0][mt][nt][ri] + sb[coll + j];
                        float pz = acc[1][mt][nt][ri] + sb[64 + coll + j];
                        float rr = __fdividef(1.f, 1.f + __expf(-pr));
                        float zz = __fdividef(1.f, 1.f + __expf(-pz));
                        float pn = (acc[2][mt][nt][ri] + sb[128 + coll + j])
                                 + rr * (acc[3][mt][nt][ri] + sb[192 + coll + j]);
                        float ttv = __expf(-2.f * fabsf(pn));
                        float nn = copysignf(__fdividef(1.f - ttv, 1.f + ttv), pn);
                        float hv = j ? h2.y : h2.x;
                        o[j] = nn + zz * (hv - nn);
                    }
                    *reinterpret_cast<float2*>(out + base) = make_float2(o[0], o[1]);
                }
        if (lid == 0) mbar_arrive(hmb + 8);        // hempty
    }
}

// --------------------------------------------------------------- launcher ---
extern "C" void kernel_launch(void* const* d_in, const int* in_sizes, int n_in,
                              void* d_out, int out_size) {
    const float* x   = (const float*)d_in[0];
    const float* hid = (const float*)d_in[1];
    const float* wx  = (const float*)d_in[2];
    const float* wh  = (const float*)d_in[3];
    const float* bx  = (const float*)d_in[4];
    const float* bh  = (const float*)d_in[5];
    float* out = (float*)d_out;

    cudaFuncSetAttribute(k_gru, cudaFuncAttributeMaxDynamicSharedMemorySize, SMEM_DYN);

    k_prep<<<22528, 256>>>(x, hid, wx, wh);
    k_gru<<<GRID, NTHREADS, SMEM_DYN>>>(hid, bx, bh, out);
}